// round 4
// baseline (speedup 1.0000x reference)
#include <cuda_runtime.h>
#include <cstdint>

// Problem constants
#define N_HEADS 1024   // B*P*H
#define I_DIM   256
#define J_DIM   256
#define D_DIM   64
#define ITILE   128
#define JTILE   64
#define INV_T   0.125f

// SMEM strides (floats), conflict-free for the fragment LDS patterns:
//  K/Q pattern (addr = row*st + qd, row varies over 8 via g): st % 32 == 4
//  V pattern   (addr = (8ks+qd)*st + g):                      st % 32 == 8
#define SQ_STRIDE 68
#define SK_STRIDE 68
#define SV_STRIDE 72

#define SQ_ELEMS (ITILE * SQ_STRIDE)            // 8704
#define SK_ELEMS (JTILE * SK_STRIDE)            // 4352
#define SV_ELEMS (JTILE * SV_STRIDE)            // 4608
#define SMEM_FLOATS (SQ_ELEMS + 2*SK_ELEMS + 2*SV_ELEMS)   // 26624
#define SMEM_BYTES  (SMEM_FLOATS * 4)           // 106496 -> 2 CTAs/SM

__device__ __forceinline__ float f2tf(float x) {
    uint32_t u;
    asm("cvt.rna.tf32.f32 %0, %1;" : "=r"(u) : "f"(x));   // unbiased tf32 rounding
    return __uint_as_float(u);
}

__device__ __forceinline__ void mma_tf32(float c[4], const uint32_t a[4], const uint32_t b[2]) {
    asm volatile(
        "mma.sync.aligned.m16n8k8.row.col.f32.tf32.tf32.f32 "
        "{%0,%1,%2,%3}, {%4,%5,%6,%7}, {%8,%9}, {%0,%1,%2,%3};"
        : "+f"(c[0]), "+f"(c[1]), "+f"(c[2]), "+f"(c[3])
        : "r"(a[0]), "r"(a[1]), "r"(a[2]), "r"(a[3]),
          "r"(b[0]), "r"(b[1]));
}

__device__ __forceinline__ void cp_async16(float* smem_dst, const float* gsrc) {
    uint32_t s = (uint32_t)__cvta_generic_to_shared(smem_dst);
    asm volatile("cp.async.ca.shared.global [%0], [%1], 16;" :: "r"(s), "l"(gsrc));
}
__device__ __forceinline__ void cp_commit() { asm volatile("cp.async.commit_group;"); }
__device__ __forceinline__ void cp_wait_all() { asm volatile("cp.async.wait_group 0;"); }

__global__ void __launch_bounds__(256, 2)
attn_kernel(const float* __restrict__ q, const float* __restrict__ k,
            const float* __restrict__ v, const float* __restrict__ pos,
            const float* __restrict__ mask, float* __restrict__ out)
{
    extern __shared__ float smem[];
    float* sQ  = smem;
    float* sKb[2] = { sQ + SQ_ELEMS, sQ + SQ_ELEMS + SK_ELEMS };
    float* sVb[2] = { sKb[1] + SK_ELEMS, sKb[1] + SK_ELEMS + SV_ELEMS };

    const int bx   = blockIdx.x;
    const int head = bx >> 1;
    const int i0   = (bx & 1) * ITILE;
    const int tid  = threadIdx.x;
    const int warp = tid >> 5;
    const int lane = tid & 31;
    const int g    = lane >> 2;
    const int qd   = lane & 3;
    const int rw   = warp * 16;   // warp's 16-row slice of the 128-row tile

    const float* qh = q + ((size_t)head * I_DIM + i0) * D_DIM;
    const float* kh = k + (size_t)head * J_DIM * D_DIM;
    const float* vh = v + (size_t)head * J_DIM * D_DIM;
    const size_t pmBase = (size_t)head * I_DIM * J_DIM;

    // ---- prologue: kick cp.async K/V for jt=0 into buffer 0 ----
    #pragma unroll
    for (int it = 0; it < 4; it++) {
        int f4  = it * 256 + tid;           // 0..1023
        int row = f4 >> 4;
        int c4  = (f4 & 15) << 2;
        cp_async16(sKb[0] + row * SK_STRIDE + c4, kh + row * D_DIM + c4);
        cp_async16(sVb[0] + row * SV_STRIDE + c4, vh + row * D_DIM + c4);
    }
    cp_commit();

    // ---- stage Q tile [128,64] -> sQ (tf32-rounded), overlaps with cp.async ----
    #pragma unroll
    for (int it = 0; it < 8; it++) {
        int f4  = it * 256 + tid;           // 0..2047
        int row = f4 >> 4;
        int c4  = (f4 & 15) << 2;
        float4 x = *(const float4*)(qh + row * D_DIM + c4);
        float* d = sQ + row * SQ_STRIDE + c4;
        d[0] = f2tf(x.x); d[1] = f2tf(x.y); d[2] = f2tf(x.z); d[3] = f2tf(x.w);
    }

    float lsum[2] = {0.f, 0.f};
    float O[8][4];
    #pragma unroll
    for (int b = 0; b < 8; b++)
        #pragma unroll
        for (int c = 0; c < 4; c++) O[b][c] = 0.f;

    for (int jt = 0; jt < 4; jt++) {
        const int j0  = jt * JTILE;
        const int cur = jt & 1;

        cp_wait_all();       // K/V(jt) resident
        __syncthreads();     // all warps past PV(jt-1) reads of buffer cur^1

        if (jt < 3) {        // stream K/V(jt+1) during the work below
            const float* khn = kh + (size_t)(j0 + JTILE) * D_DIM;
            const float* vhn = vh + (size_t)(j0 + JTILE) * D_DIM;
            #pragma unroll
            for (int it = 0; it < 4; it++) {
                int f4  = it * 256 + tid;
                int row = f4 >> 4;
                int c4  = (f4 & 15) << 2;
                cp_async16(sKb[cur ^ 1] + row * SK_STRIDE + c4, khn + row * D_DIM + c4);
                cp_async16(sVb[cur ^ 1] + row * SV_STRIDE + c4, vhn + row * D_DIM + c4);
            }
            cp_commit();
        }

        // ---- in-place tf32-rna rounding pass on K/V(jt) (removes per-fragment cvt) ----
        {
            float* kb = sKb[cur];
            float* vb = sVb[cur];
            #pragma unroll
            for (int it = 0; it < 4; it++) {
                int f4  = it * 256 + tid;
                int row = f4 >> 4;
                int c4  = (f4 & 15) << 2;
                float4* ka = (float4*)(kb + row * SK_STRIDE + c4);
                float4 x = *ka;
                *ka = make_float4(f2tf(x.x), f2tf(x.y), f2tf(x.z), f2tf(x.w));
                float4* va = (float4*)(vb + row * SV_STRIDE + c4);
                float4 y = *va;
                *va = make_float4(f2tf(y.x), f2tf(y.y), f2tf(y.z), f2tf(y.w));
            }
        }
        __syncthreads();

        const float* sK = sKb[cur];
        const float* sV = sVb[cur];

        // ---- S = Q * K^T : warp tile M16 x N64 ----
        float S[8][4];
        #pragma unroll
        for (int b = 0; b < 8; b++)
            #pragma unroll
            for (int c = 0; c < 4; c++) S[b][c] = 0.f;

        #pragma unroll
        for (int ks = 0; ks < 8; ks++) {
            uint32_t a[4];
            const float* base = sQ + rw * SQ_STRIDE + ks * 8;
            a[0] = __float_as_uint(base[g * SQ_STRIDE + qd]);
            a[1] = __float_as_uint(base[(g + 8) * SQ_STRIDE + qd]);
            a[2] = __float_as_uint(base[g * SQ_STRIDE + qd + 4]);
            a[3] = __float_as_uint(base[(g + 8) * SQ_STRIDE + qd + 4]);
            #pragma unroll
            for (int nb = 0; nb < 8; nb++) {
                uint32_t b[2];
                const float* kp = sK + (nb * 8 + g) * SK_STRIDE + ks * 8 + qd;
                b[0] = __float_as_uint(kp[0]);
                b[1] = __float_as_uint(kp[4]);
                mma_tf32(S[nb], a, b);
            }
        }

        // ---- epilogue: p = exp(mask*(S/8+pos)) (no max shift), P tf32-rounded ----
        #pragma unroll
        for (int half = 0; half < 2; half++) {
            const int rr = half * 2;              // regs {0,1}: row g ; {2,3}: row g+8
            const int r  = i0 + rw + g + half * 8;
            const float2* prow = (const float2*)(pos  + pmBase + (size_t)r * J_DIM + j0) + qd;
            const float2* mrow = (const float2*)(mask + pmBase + (size_t)r * J_DIM + j0) + qd;

            float2 pp[8], mm[8];
            #pragma unroll
            for (int nb = 0; nb < 8; nb++) {      // 16 independent streaming loads
                pp[nb] = __ldcs(prow + nb * 4);
                mm[nb] = __ldcs(mrow + nb * 4);
            }
            float acc = 0.f;
            #pragma unroll
            for (int nb = 0; nb < 8; nb++) {
                float s0 = mm[nb].x * fmaf(S[nb][rr + 0], INV_T, pp[nb].x);
                float s1 = mm[nb].y * fmaf(S[nb][rr + 1], INV_T, pp[nb].y);
                float p0 = f2tf(__expf(s0));
                float p1 = f2tf(__expf(s1));
                S[nb][rr + 0] = p0; S[nb][rr + 1] = p1;
                acc += p0 + p1;
            }
            lsum[half] += acc;
        }

        // ---- O += P * V ; P fragments via intra-quad shuffles (no SMEM trip) ----
        const bool odd = qd & 1;
        const int l0 = (lane & 28) | (qd >> 1);
        const int l1 = l0 + 2;
        #pragma unroll
        for (int ks = 0; ks < 8; ks++) {
            float t00 = __shfl_sync(0xffffffffu, S[ks][0], l0);
            float t01 = __shfl_sync(0xffffffffu, S[ks][1], l0);
            float t02 = __shfl_sync(0xffffffffu, S[ks][2], l0);
            float t03 = __shfl_sync(0xffffffffu, S[ks][3], l0);
            float t10 = __shfl_sync(0xffffffffu, S[ks][0], l1);
            float t11 = __shfl_sync(0xffffffffu, S[ks][1], l1);
            float t12 = __shfl_sync(0xffffffffu, S[ks][2], l1);
            float t13 = __shfl_sync(0xffffffffu, S[ks][3], l1);
            uint32_t a[4];
            a[0] = __float_as_uint(odd ? t01 : t00);   // P[g   ][8ks+qd]
            a[1] = __float_as_uint(odd ? t03 : t02);   // P[g+8 ][8ks+qd]
            a[2] = __float_as_uint(odd ? t11 : t10);   // P[g   ][8ks+qd+4]
            a[3] = __float_as_uint(odd ? t13 : t12);   // P[g+8 ][8ks+qd+4]
            #pragma unroll
            for (int nd = 0; nd < 8; nd++) {
                uint32_t b[2];
                const float* vb = sV + (ks * 8 + qd) * SV_STRIDE + nd * 8 + g;
                b[0] = __float_as_uint(vb[0]);
                b[1] = __float_as_uint(vb[4 * SV_STRIDE]);
                mma_tf32(O[nd], a, b);
            }
        }
    }

    // ---- final quad reduction of lsum, normalize, write out ----
    #pragma unroll
    for (int half = 0; half < 2; half++) {
        lsum[half] += __shfl_xor_sync(0xffffffffu, lsum[half], 1);
        lsum[half] += __shfl_xor_sync(0xffffffffu, lsum[half], 2);
    }
    float inv0 = 1.f / lsum[0];
    float inv1 = 1.f / lsum[1];
    int r0 = i0 + rw + g;
    float* o0 = out + ((size_t)head * I_DIM + r0) * D_DIM;
    float* o1 = o0 + 8 * D_DIM;
    #pragma unroll
    for (int nd = 0; nd < 8; nd++) {
        int c = nd * 8 + qd * 2;
        *(float2*)(o0 + c) = make_float2(O[nd][0] * inv0, O[nd][1] * inv0);
        *(float2*)(o1 + c) = make_float2(O[nd][2] * inv1, O[nd][3] * inv1);
    }
}

extern "C" void kernel_launch(void* const* d_in, const int* in_sizes, int n_in,
                              void* d_out, int out_size)
{
    const float* q    = (const float*)d_in[0];
    const float* k    = (const float*)d_in[1];
    const float* v    = (const float*)d_in[2];
    const float* pos  = (const float*)d_in[3];
    const float* mask = (const float*)d_in[4];
    float* out = (float*)d_out;

    cudaFuncSetAttribute(attn_kernel, cudaFuncAttributeMaxDynamicSharedMemorySize, SMEM_BYTES);

    dim3 grid(N_HEADS * (I_DIM / ITILE));   // 2048 CTAs
    dim3 block(256);
    attn_kernel<<<grid, block, SMEM_BYTES>>>(q, k, v, pos, mask, out);
}

// round 6
// speedup vs baseline: 1.4045x; 1.4045x over previous
#include <cuda_runtime.h>
#include <cstdint>

// Problem constants
#define N_HEADS 1024   // B*P*H
#define I_DIM   256
#define J_DIM   256
#define D_DIM   64
#define ITILE   128
#define JTILE   64
#define INV_T   0.125f

// SMEM strides (floats). Conflict-free fragment LDS:
//  Q/K/P pattern (row varies over 8 via g, col = qd): stride % 32 == 4
//  V pattern     (row = 8ks+qd, col = g):             stride % 32 == 8
#define SQ_STRIDE 68
#define SK_STRIDE 68
#define SV_STRIDE 72
#define SP_STRIDE 68

#define SQ_ELEMS (ITILE * SQ_STRIDE)   // 8704
#define SK_ELEMS (JTILE * SK_STRIDE)   // 4352
#define SV_ELEMS (JTILE * SV_STRIDE)   // 4608
#define SP_ELEMS (ITILE * SP_STRIDE)   // 8704
#define SMEM_FLOATS (SQ_ELEMS + SK_ELEMS + SV_ELEMS + SP_ELEMS)
#define SMEM_BYTES  (SMEM_FLOATS * 4)  // 105472 -> 2 CTAs/SM

__device__ __forceinline__ float f2tf(float x) {
    uint32_t u;
    asm("cvt.rna.tf32.f32 %0, %1;" : "=r"(u) : "f"(x));   // unbiased tf32 rounding
    return __uint_as_float(u);
}

__device__ __forceinline__ void mma_tf32(float c[4], const uint32_t a[4], const uint32_t b[2]) {
    asm volatile(
        "mma.sync.aligned.m16n8k8.row.col.f32.tf32.tf32.f32 "
        "{%0,%1,%2,%3}, {%4,%5,%6,%7}, {%8,%9}, {%0,%1,%2,%3};"
        : "+f"(c[0]), "+f"(c[1]), "+f"(c[2]), "+f"(c[3])
        : "r"(a[0]), "r"(a[1]), "r"(a[2]), "r"(a[3]),
          "r"(b[0]), "r"(b[1]));
}

// load one pos/mask stage (mb,half) for j-tile jtv into register buffers
#define LOAD_STAGE(PP, MM, jtv, mbv, halfv) do {                                          \
    int r_ = i0 + rw + (mbv) * 16 + (halfv) * 8 + g;                                      \
    const float2* p_ = (const float2*)(pos  + pmBase + (size_t)r_ * J_DIM + (jtv) * JTILE) + qd; \
    const float2* m_ = (const float2*)(mask + pmBase + (size_t)r_ * J_DIM + (jtv) * JTILE) + qd; \
    _Pragma("unroll")                                                                     \
    for (int nb_ = 0; nb_ < 8; nb_++) {                                                   \
        PP[nb_] = __ldcs(p_ + nb_ * 4);                                                   \
        MM[nb_] = __ldcs(m_ + nb_ * 4);                                                   \
    }                                                                                     \
} while (0)

// process one stage: s = mask*(S/8 + pos); p = tf32(exp(s)); accumulate lsum
#define PROC_STAGE(PP, MM, mbv, halfv) do {                                               \
    const int rr_ = (halfv) * 2;                                                          \
    float acc_ = 0.f;                                                                     \
    _Pragma("unroll")                                                                     \
    for (int nb_ = 0; nb_ < 8; nb_++) {                                                   \
        float s0_ = MM[nb_].x * fmaf(S[mbv][nb_][rr_ + 0], INV_T, PP[nb_].x);             \
        float s1_ = MM[nb_].y * fmaf(S[mbv][nb_][rr_ + 1], INV_T, PP[nb_].y);             \
        float p0_ = f2tf(__expf(s0_));                                                    \
        float p1_ = f2tf(__expf(s1_));                                                    \
        S[mbv][nb_][rr_ + 0] = p0_;                                                       \
        S[mbv][nb_][rr_ + 1] = p1_;                                                       \
        acc_ += p0_ + p1_;                                                                \
    }                                                                                     \
    lsum[mbv][halfv] += acc_;                                                             \
} while (0)

__global__ void __launch_bounds__(128, 2)
attn_kernel(const float* __restrict__ q, const float* __restrict__ k,
            const float* __restrict__ v, const float* __restrict__ pos,
            const float* __restrict__ mask, float* __restrict__ out)
{
    extern __shared__ float smem[];
    float* sQ = smem;
    float* sK = sQ + SQ_ELEMS;
    float* sV = sK + SK_ELEMS;
    float* sP = sV + SV_ELEMS;

    const int bx   = blockIdx.x;
    const int head = bx >> 1;
    const int i0   = (bx & 1) * ITILE;
    const int tid  = threadIdx.x;
    const int warp = tid >> 5;
    const int lane = tid & 31;
    const int g    = lane >> 2;   // row group within fragment (0..7)
    const int qd   = lane & 3;    // quad column (0..3)
    const int rw   = warp * 32;   // warp's row base within the 128-row tile

    const float* qh = q + ((size_t)head * I_DIM + i0) * D_DIM;
    const float* kh = k + (size_t)head * J_DIM * D_DIM;
    const float* vh = v + (size_t)head * J_DIM * D_DIM;
    const size_t pmBase = (size_t)head * I_DIM * J_DIM;

    // pos/mask register stage buffers (software pipeline, no new syncs)
    float2 ppA[8], mmA[8], ppB[8], mmB[8];

    // stage0 of jt=0 in flight ASAP (covered by Q staging + jt0 K/V staging + QK)
    LOAD_STAGE(ppA, mmA, 0, 0, 0);

    // ---- Load Q tile [128,64] -> sQ (tf32-rounded) ----
    #pragma unroll
    for (int it = 0; it < 16; it++) {
        int f4  = it * 128 + tid;          // 0..2047 float4s
        int row = f4 >> 4;
        int c4  = (f4 & 15) << 2;
        float4 x = *(const float4*)(qh + row * D_DIM + c4);
        float* d = sQ + row * SQ_STRIDE + c4;
        d[0] = f2tf(x.x); d[1] = f2tf(x.y); d[2] = f2tf(x.z); d[3] = f2tf(x.w);
    }

    float lsum[2][2] = {{0.f, 0.f}, {0.f, 0.f}};
    float O[2][8][4];
    #pragma unroll
    for (int a = 0; a < 2; a++)
        #pragma unroll
        for (int b = 0; b < 8; b++)
            #pragma unroll
            for (int c = 0; c < 4; c++) O[a][b][c] = 0.f;

    for (int jt = 0; jt < 4; jt++) {
        const int j0 = jt * JTILE;
        __syncthreads();   // prev iter done reading sK/sV; prev PV done reading sP

        // ---- Load K,V tiles [64,64] -> smem (tf32-rounded) ----
        #pragma unroll
        for (int it = 0; it < 8; it++) {
            int f4  = it * 128 + tid;      // 0..1023
            int row = f4 >> 4;
            int c4  = (f4 & 15) << 2;
            float4 x = *(const float4*)(kh + (size_t)(j0 + row) * D_DIM + c4);
            float* d = sK + row * SK_STRIDE + c4;
            d[0] = f2tf(x.x); d[1] = f2tf(x.y); d[2] = f2tf(x.z); d[3] = f2tf(x.w);
            float4 y = *(const float4*)(vh + (size_t)(j0 + row) * D_DIM + c4);
            float* e = sV + row * SV_STRIDE + c4;
            e[0] = f2tf(y.x); e[1] = f2tf(y.y); e[2] = f2tf(y.z); e[3] = f2tf(y.w);
        }
        __syncthreads();

        // stage1(jt) loads — covered by the QK MMA phase below
        LOAD_STAGE(ppB, mmB, jt, 0, 1);

        // ---- S = Q * K^T for this J-tile: warp tile M32 x N64 ----
        float S[2][8][4];
        #pragma unroll
        for (int a = 0; a < 2; a++)
            #pragma unroll
            for (int b = 0; b < 8; b++)
                #pragma unroll
                for (int c = 0; c < 4; c++) S[a][b][c] = 0.f;

        #pragma unroll
        for (int ks = 0; ks < 8; ks++) {
            uint32_t a[2][4];
            #pragma unroll
            for (int mb = 0; mb < 2; mb++) {
                const float* base = sQ + (rw + mb * 16) * SQ_STRIDE + ks * 8;
                a[mb][0] = __float_as_uint(base[g * SQ_STRIDE + qd]);
                a[mb][1] = __float_as_uint(base[(g + 8) * SQ_STRIDE + qd]);
                a[mb][2] = __float_as_uint(base[g * SQ_STRIDE + qd + 4]);
                a[mb][3] = __float_as_uint(base[(g + 8) * SQ_STRIDE + qd + 4]);
            }
            #pragma unroll
            for (int nb = 0; nb < 8; nb++) {
                uint32_t b[2];
                const float* kb = sK + (nb * 8 + g) * SK_STRIDE + ks * 8 + qd;
                b[0] = __float_as_uint(kb[0]);
                b[1] = __float_as_uint(kb[4]);
                mma_tf32(S[0][nb], a[0], b);
                mma_tf32(S[1][nb], a[1], b);
            }
        }

        // ---- epilogue: 4 pipelined stages (A/B register ping-pong) ----
        PROC_STAGE(ppA, mmA, 0, 0);        // stage0 (loaded during prev PV / prologue)
        LOAD_STAGE(ppA, mmA, jt, 1, 0);    // stage2 loads behind stage1 processing
        PROC_STAGE(ppB, mmB, 0, 1);        // stage1 (loaded pre-QK)
        LOAD_STAGE(ppB, mmB, jt, 1, 1);    // stage3 loads behind stage2 processing
        PROC_STAGE(ppA, mmA, 1, 0);        // stage2
        PROC_STAGE(ppB, mmB, 1, 1);        // stage3

        // ---- store P to sP in [i][j] layout (already tf32-rounded) ----
        #pragma unroll
        for (int mb = 0; mb < 2; mb++) {
            float* pbase = sP + (rw + mb * 16) * SP_STRIDE;
            #pragma unroll
            for (int nb = 0; nb < 8; nb++) {
                int c = nb * 8 + qd * 2;
                float2 v0 = make_float2(S[mb][nb][0], S[mb][nb][1]);
                float2 v1 = make_float2(S[mb][nb][2], S[mb][nb][3]);
                *(float2*)(pbase + g * SP_STRIDE + c)       = v0;
                *(float2*)(pbase + (g + 8) * SP_STRIDE + c) = v1;
            }
        }
        __syncthreads();

        // stage0(jt+1) loads — covered by the PV MMA phase below
        if (jt < 3) LOAD_STAGE(ppA, mmA, jt + 1, 0, 0);

        // ---- O += P * V  (A = sP [M x 64j], B = sV [64j x 64d]) ----
        #pragma unroll
        for (int ks = 0; ks < 8; ks++) {
            uint32_t a[2][4];
            #pragma unroll
            for (int mb = 0; mb < 2; mb++) {
                const float* base = sP + (rw + mb * 16) * SP_STRIDE + ks * 8;
                a[mb][0] = __float_as_uint(base[g * SP_STRIDE + qd]);
                a[mb][1] = __float_as_uint(base[(g + 8) * SP_STRIDE + qd]);
                a[mb][2] = __float_as_uint(base[g * SP_STRIDE + qd + 4]);
                a[mb][3] = __float_as_uint(base[(g + 8) * SP_STRIDE + qd + 4]);
            }
            #pragma unroll
            for (int nd = 0; nd < 8; nd++) {
                uint32_t b[2];
                const float* vb = sV + (ks * 8 + qd) * SV_STRIDE + nd * 8 + g;
                b[0] = __float_as_uint(vb[0]);
                b[1] = __float_as_uint(vb[4 * SV_STRIDE]);
                mma_tf32(O[0][nd], a[0], b);
                mma_tf32(O[1][nd], a[1], b);
            }
        }
    }

    // ---- final quad reduction of lsum, normalize, write out ----
    #pragma unroll
    for (int mb = 0; mb < 2; mb++)
        #pragma unroll
        for (int half = 0; half < 2; half++) {
            lsum[mb][half] += __shfl_xor_sync(0xffffffffu, lsum[mb][half], 1);
            lsum[mb][half] += __shfl_xor_sync(0xffffffffu, lsum[mb][half], 2);
        }

    #pragma unroll
    for (int mb = 0; mb < 2; mb++) {
        float inv0 = 1.f / lsum[mb][0];
        float inv1 = 1.f / lsum[mb][1];
        int r0 = i0 + rw + mb * 16 + g;
        float* o0 = out + ((size_t)head * I_DIM + r0) * D_DIM;
        float* o1 = o0 + 8 * D_DIM;
        #pragma unroll
        for (int nd = 0; nd < 8; nd++) {
            int c = nd * 8 + qd * 2;
            *(float2*)(o0 + c) = make_float2(O[mb][nd][0] * inv0, O[mb][nd][1] * inv0);
            *(float2*)(o1 + c) = make_float2(O[mb][nd][2] * inv1, O[mb][nd][3] * inv1);
        }
    }
}

extern "C" void kernel_launch(void* const* d_in, const int* in_sizes, int n_in,
                              void* d_out, int out_size)
{
    const float* q    = (const float*)d_in[0];
    const float* k    = (const float*)d_in[1];
    const float* v    = (const float*)d_in[2];
    const float* pos  = (const float*)d_in[3];
    const float* mask = (const float*)d_in[4];
    float* out = (float*)d_out;

    cudaFuncSetAttribute(attn_kernel, cudaFuncAttributeMaxDynamicSharedMemorySize, SMEM_BYTES);

    dim3 grid(N_HEADS * (I_DIM / ITILE));   // 2048 CTAs
    dim3 block(128);
    attn_kernel<<<grid, block, SMEM_BYTES>>>(q, k, v, pos, mask, out);
}